// round 1
// baseline (speedup 1.0000x reference)
#include <cuda_runtime.h>

// Problem constants (fixed by the dataset)
#define B_    64
#define OBJS_ 2048
#define D_    256
#define K_    2
#define N_    (B_*OBJS_)          // 131072
#define BDK   (B_*D_*K_)          // 32768
#define NK    (N_*K_)             // 262144

// Wave blocking: 32 scenes/wave = 64 MB working set, fits GB300 L2 (~126 MB)
#define SPW   32                  // scenes per wave
#define WAVES (B_/SPW)            // 2
#define CPS   16                  // CTAs per scene
#define ROWS_PER_CTA (OBJS_/CPS)  // 128
#define THREADS 256
#define NWARP 8
#define ROWS_PER_WARP (ROWS_PER_CTA/NWARP) // 16

// Scratch (device globals: allocation-free rule)
__device__ float g_ctxsum[B_*D_];   // per-scene column sums
__device__ float g_zsum[B_*K_];     // per-scene softmax denominators
__device__ float g_feat[BDK];       // unnormalized pooled features
__device__ float g_z[NK];           // per-object unnormalized softmax numerators
__device__ float g_bt[K_];          // bias_term = channel_bias @ att_shared

// ---------------------------------------------------------------------------
// Kernel 1: zero scratch + compute bias_term (cheap, 1 graph node)
// ---------------------------------------------------------------------------
__global__ void zeroK(const float* __restrict__ cb, const float* __restrict__ att)
{
    int i = blockIdx.x * blockDim.x + threadIdx.x;
    if (i < B_*D_)  g_ctxsum[i] = 0.f;
    if (i < B_*K_)  g_zsum[i]   = 0.f;
    if (i < BDK)    g_feat[i]   = 0.f;

    if (blockIdx.x == 0 && threadIdx.x < 64) {
        int k = threadIdx.x >> 5, lane = threadIdx.x & 31;
        float s = 0.f;
        #pragma unroll
        for (int j = 0; j < 8; j++)
            s += cb[k*D_ + lane + 32*j] * att[lane + 32*j];
        #pragma unroll
        for (int m = 16; m; m >>= 1)
            s += __shfl_xor_sync(0xffffffffu, s, m);
        if (lane == 0) g_bt[k] = s;
    }
}

// ---------------------------------------------------------------------------
// Kernel 2 (per wave): per-scene column sums (first pass over x, DRAM-bound)
// ---------------------------------------------------------------------------
__global__ __launch_bounds__(THREADS) void sumK(const float* __restrict__ x, int wave)
{
    int cta   = blockIdx.x;               // SPW*CPS = 512 CTAs
    int b     = wave*SPW + cta / CPS;
    int chunk = cta % CPS;
    size_t base = ((size_t)b*OBJS_ + (size_t)chunk*ROWS_PER_CTA) * D_ + threadIdx.x;

    float a0 = 0.f, a1 = 0.f, a2 = 0.f, a3 = 0.f;
    #pragma unroll 4
    for (int r = 0; r < ROWS_PER_CTA; r += 4) {
        a0 += x[base + (size_t)(r+0)*D_];
        a1 += x[base + (size_t)(r+1)*D_];
        a2 += x[base + (size_t)(r+2)*D_];
        a3 += x[base + (size_t)(r+3)*D_];
    }
    atomicAdd(&g_ctxsum[b*D_ + threadIdx.x], (a0+a1) + (a2+a3));
}

// ---------------------------------------------------------------------------
// Kernel 3 (per wave): fused logits + exp + unnormalized weighted pooling
// (second pass over x, should hit L2 from the same wave's sumK)
// Each warp owns whole rows; lane covers cols {4l..4l+3, 128+4l..128+4l+3}.
// ---------------------------------------------------------------------------
__global__ __launch_bounds__(THREADS, 2) void mainK(
    const float* __restrict__ x,
    const float* __restrict__ att,
    const float* __restrict__ scale,
    const int*   __restrict__ num_objs,
    int wave)
{
    __shared__ float sfeat[D_*K_];        // 2 KB per-CTA feature accumulator

    int cta   = blockIdx.x;
    int b     = wave*SPW + cta / CPS;
    int chunk = cta % CPS;
    int warp  = threadIdx.x >> 5, lane = threadIdx.x & 31;

    for (int i = threadIdx.x; i < D_*K_; i += THREADS) sfeat[i] = 0.f;

    float bt0 = g_bt[0], bt1 = g_bt[1];
    float s0  = scale[0], s1 = scale[1];
    float invc = 1.f / fmaxf((float)num_objs[b], 1.f);

    // per-lane invariant ctx (= mean) and att_shared values
    const float4* ctxp = (const float4*)(g_ctxsum + b*D_);
    float4 ctxa = ctxp[lane], ctxb = ctxp[lane + 32];
    ctxa.x *= invc; ctxa.y *= invc; ctxa.z *= invc; ctxa.w *= invc;
    ctxb.x *= invc; ctxb.y *= invc; ctxb.z *= invc; ctxb.w *= invc;
    const float4* ap = (const float4*)att;
    float4 aa = ap[lane], ab = ap[lane + 32];

    __syncthreads();

    float zs0 = 0.f, zs1 = 0.f;
    float4 f0a = {0,0,0,0}, f0b = {0,0,0,0};   // k=0 feature accum
    float4 f1a = {0,0,0,0}, f1b = {0,0,0,0};   // k=1 feature accum

    int rowbase = b*OBJS_ + chunk*ROWS_PER_CTA + warp;

    #pragma unroll 2
    for (int r = 0; r < ROWS_PER_WARP; r++) {
        int row = rowbase + r*NWARP;
        const float4* xr = (const float4*)(x + (size_t)row * D_);
        float4 xa = xr[lane];
        float4 xb = xr[lane + 32];

        // base = sum_d lrelu(x+ctx, 0.2) * att_shared[d]
        float t, acc;
        t = xa.x + ctxa.x; acc  = aa.x * fmaxf(t, 0.2f*t);
        t = xa.y + ctxa.y; acc += aa.y * fmaxf(t, 0.2f*t);
        t = xa.z + ctxa.z; acc += aa.z * fmaxf(t, 0.2f*t);
        t = xa.w + ctxa.w; acc += aa.w * fmaxf(t, 0.2f*t);
        t = xb.x + ctxb.x; acc += ab.x * fmaxf(t, 0.2f*t);
        t = xb.y + ctxb.y; acc += ab.y * fmaxf(t, 0.2f*t);
        t = xb.z + ctxb.z; acc += ab.z * fmaxf(t, 0.2f*t);
        t = xb.w + ctxb.w; acc += ab.w * fmaxf(t, 0.2f*t);

        #pragma unroll
        for (int m = 16; m; m >>= 1)
            acc += __shfl_xor_sync(0xffffffffu, acc, m);

        // unnormalized softmax numerators (no max-shift needed: |logit| < ~25)
        float z0 = __expf((acc + bt0) * s0);
        float z1 = __expf((acc + bt1) * s1);
        zs0 += z0; zs1 += z1;
        if (lane == 0)
            *(float2*)(g_z + (size_t)row * 2) = make_float2(z0, z1);

        // unnormalized pooled features
        f0a.x += xa.x*z0; f0a.y += xa.y*z0; f0a.z += xa.z*z0; f0a.w += xa.w*z0;
        f0b.x += xb.x*z0; f0b.y += xb.y*z0; f0b.z += xb.z*z0; f0b.w += xb.w*z0;
        f1a.x += xa.x*z1; f1a.y += xa.y*z1; f1a.z += xa.z*z1; f1a.w += xa.w*z1;
        f1b.x += xb.x*z1; f1b.y += xb.y*z1; f1b.z += xb.z*z1; f1b.w += xb.w*z1;
    }

    // combine warps: within a warp lanes hit distinct addrs; across 8 warps smem atomics
    int c0 = 4*lane, c1 = 128 + 4*lane;
    atomicAdd(&sfeat[(c0+0)*2+0], f0a.x); atomicAdd(&sfeat[(c0+0)*2+1], f1a.x);
    atomicAdd(&sfeat[(c0+1)*2+0], f0a.y); atomicAdd(&sfeat[(c0+1)*2+1], f1a.y);
    atomicAdd(&sfeat[(c0+2)*2+0], f0a.z); atomicAdd(&sfeat[(c0+2)*2+1], f1a.z);
    atomicAdd(&sfeat[(c0+3)*2+0], f0a.w); atomicAdd(&sfeat[(c0+3)*2+1], f1a.w);
    atomicAdd(&sfeat[(c1+0)*2+0], f0b.x); atomicAdd(&sfeat[(c1+0)*2+1], f1b.x);
    atomicAdd(&sfeat[(c1+1)*2+0], f0b.y); atomicAdd(&sfeat[(c1+1)*2+1], f1b.y);
    atomicAdd(&sfeat[(c1+2)*2+0], f0b.z); atomicAdd(&sfeat[(c1+2)*2+1], f1b.z);
    atomicAdd(&sfeat[(c1+3)*2+0], f0b.w); atomicAdd(&sfeat[(c1+3)*2+1], f1b.w);

    if (lane == 0) {
        atomicAdd(&g_zsum[b*2 + 0], zs0);
        atomicAdd(&g_zsum[b*2 + 1], zs1);
    }
    __syncthreads();
    for (int i = threadIdx.x; i < D_*K_; i += THREADS)
        atomicAdd(&g_feat[b*D_*K_ + i], sfeat[i]);
}

// ---------------------------------------------------------------------------
// Kernel 4: normalize + write outputs (scene_features then attn_weights)
// ---------------------------------------------------------------------------
__global__ void finalK(float* __restrict__ out, int out_size)
{
    int i = blockIdx.x * blockDim.x + threadIdx.x;
    if (out_size >= BDK + NK) {
        if (i < BDK) {
            int b = i >> 9;                       // D*K = 512
            out[i] = g_feat[i] / g_zsum[b*2 + (i & 1)];
        } else if (i < BDK + NK) {
            int j = i - BDK;
            int b = (j >> 1) >> 11;               // OBJS = 2048
            out[i] = g_z[j] / g_zsum[b*2 + (j & 1)];
        }
    } else if (out_size == BDK) {
        if (i < BDK) {
            int b = i >> 9;
            out[i] = g_feat[i] / g_zsum[b*2 + (i & 1)];
        }
    } else {  // attn-weights-only fallback
        if (i < NK && i < out_size) {
            int b = (i >> 1) >> 11;
            out[i] = g_z[i] / g_zsum[b*2 + (i & 1)];
        }
    }
}

// ---------------------------------------------------------------------------
extern "C" void kernel_launch(void* const* d_in, const int* in_sizes, int n_in,
                              void* d_out, int out_size)
{
    const float* x         = (const float*)d_in[0];  // [N, D]
    const int*   num_objs  = (const int*)  d_in[1];  // [B]
    const float* att       = (const float*)d_in[2];  // [1, D]
    const float* scale     = (const float*)d_in[3];  // [K, 1]
    const float* cb        = (const float*)d_in[4];  // [K, D]
    float*       out       = (float*)d_out;

    zeroK<<<(BDK + 255)/256, 256>>>(cb, att);

    for (int w = 0; w < WAVES; w++) {
        sumK <<<SPW*CPS, THREADS>>>(x, w);
        mainK<<<SPW*CPS, THREADS>>>(x, att, scale, num_objs, w);
    }

    int total = BDK + NK;
    finalK<<<(total + 255)/256, 256>>>(out, out_size);
}

// round 2
// speedup vs baseline: 1.3514x; 1.3514x over previous
#include <cuda_runtime.h>

// Problem constants (fixed by the dataset)
#define B_    64
#define OBJS_ 2048
#define D_    256
#define K_    2
#define N_    (B_*OBJS_)          // 131072
#define BDK   (B_*D_*K_)          // 32768
#define NK    (N_*K_)             // 262144

#define CPS   8                   // CTAs per scene
#define ROWS_PER_CTA (OBJS_/CPS)  // 256
#define THREADS 256
#define NWARP 8
#define ROWS_PER_WARP (ROWS_PER_CTA/NWARP) // 32
#define NCTA  (B_*CPS)            // 512

// Scratch (device globals — allocation-free rule). Per-CTA partial slots with
// plain stores: nothing here needs pre-zeroing between graph replays.
__device__ float g_ctxp [NCTA*D_];     // per-CTA column-sum partials
__device__ float g_featp[NCTA*D_*K_];  // per-CTA pooled-feature partials
__device__ float g_zsump[NCTA*K_];     // per-CTA softmax-denominator partials
__device__ float g_z[NK];              // per-object unnormalized numerators
__device__ int   g_cnt[B_];            // per-scene arrival counters (reset by finalK)

// ---------------------------------------------------------------------------
// Fused kernel: pass1 (column sums) + per-scene barrier + pass2 (logits, exp,
// weighted pooling). 8 CTAs per scene, contiguous blockIdx -> deadlock-free.
// ---------------------------------------------------------------------------
__global__ __launch_bounds__(THREADS, 3) void fusedK(
    const float* __restrict__ x,
    const float* __restrict__ att,
    const float* __restrict__ scale,
    const float* __restrict__ cb,
    const int*   __restrict__ num_objs)
{
    __shared__ float sred[4*D_];      // pass1 cross-rowgroup reduce (4 KB)
    __shared__ float sctx[D_];        // per-scene mean context
    __shared__ float sfeat[D_*K_];    // pass2 feature accumulator (2 KB)
    __shared__ float sbt[K_];         // bias_term
    __shared__ float szs[K_];         // zsum accumulator

    const int cta   = blockIdx.x;
    const int b     = cta / CPS;
    const int chunk = cta % CPS;
    const int tid   = threadIdx.x;
    const int warp  = tid >> 5, lane = tid & 31;

    // ---------------- pass 1: column sums over this CTA's 256 rows ---------
    {
        const int col4   = tid & 63;          // float4 column 0..63
        const int rowgrp = tid >> 6;          // 0..3
        const float4* x4 = (const float4*)x;
        size_t idx = ((size_t)(b*OBJS_ + chunk*ROWS_PER_CTA + rowgrp))*64 + col4;
        float4 acc = {0.f,0.f,0.f,0.f};
        #pragma unroll 8
        for (int i = 0; i < ROWS_PER_CTA/4; i++) {
            float4 v = x4[idx + (size_t)i*256];   // 4 rows per step, stride 4 rows
            acc.x += v.x; acc.y += v.y; acc.z += v.z; acc.w += v.w;
        }
        *(float4*)&sred[rowgrp*D_ + col4*4] = acc;
    }
    __syncthreads();
    if (tid < D_) {
        float p = sred[tid] + sred[D_+tid] + sred[2*D_+tid] + sred[3*D_+tid];
        g_ctxp[(size_t)cta*D_ + tid] = p;
    }

    // bias_term (redundant per CTA, trivial cost) + zero pass2 accumulators
    if (tid < 64) {
        int k = tid >> 5, l = tid & 31;
        float s = 0.f;
        #pragma unroll
        for (int j = 0; j < 8; j++) s += cb[k*D_ + l + 32*j] * att[l + 32*j];
        #pragma unroll
        for (int m = 16; m; m >>= 1) s += __shfl_xor_sync(0xffffffffu, s, m);
        if (l == 0) sbt[k] = s;
    }
    for (int i = tid; i < D_*K_; i += THREADS) sfeat[i] = 0.f;
    if (tid < K_) szs[tid] = 0.f;

    // ---------------- per-scene barrier ------------------------------------
    __syncthreads();
    if (tid == 0) {
        __threadfence();
        atomicAdd(&g_cnt[b], 1);
        volatile int* c = &g_cnt[b];
        while (*c < CPS) __nanosleep(40);
        __threadfence();
    }
    __syncthreads();

    // assemble per-scene mean context from the 8 partials
    const float invc = 1.f / fmaxf((float)num_objs[b], 1.f);
    if (tid < D_) {
        float s = 0.f;
        #pragma unroll
        for (int j = 0; j < CPS; j++) s += g_ctxp[(size_t)(b*CPS + j)*D_ + tid];
        sctx[tid] = s * invc;
    }
    __syncthreads();

    // ---------------- pass 2: fused logits + exp + weighted pooling --------
    const float bt0 = sbt[0], bt1 = sbt[1];
    const float s0  = scale[0], s1 = scale[1];
    const float4* ctxp4 = (const float4*)sctx;
    float4 ctxa = ctxp4[lane], ctxb = ctxp4[lane + 32];
    const float4* ap = (const float4*)att;
    float4 aa = ap[lane], ab = ap[lane + 32];

    float zs0 = 0.f, zs1 = 0.f;
    float4 f0a = {0,0,0,0}, f0b = {0,0,0,0};
    float4 f1a = {0,0,0,0}, f1b = {0,0,0,0};

    const int rowbase = b*OBJS_ + chunk*ROWS_PER_CTA + warp*ROWS_PER_WARP;

    #pragma unroll 2
    for (int r = 0; r < ROWS_PER_WARP; r++) {
        int row = rowbase + r;
        const float4* xr = (const float4*)(x + (size_t)row * D_);
        float4 xa = xr[lane];
        float4 xb = xr[lane + 32];

        float t, acc;
        t = xa.x + ctxa.x; acc  = aa.x * fmaxf(t, 0.2f*t);
        t = xa.y + ctxa.y; acc += aa.y * fmaxf(t, 0.2f*t);
        t = xa.z + ctxa.z; acc += aa.z * fmaxf(t, 0.2f*t);
        t = xa.w + ctxa.w; acc += aa.w * fmaxf(t, 0.2f*t);
        t = xb.x + ctxb.x; acc += ab.x * fmaxf(t, 0.2f*t);
        t = xb.y + ctxb.y; acc += ab.y * fmaxf(t, 0.2f*t);
        t = xb.z + ctxb.z; acc += ab.z * fmaxf(t, 0.2f*t);
        t = xb.w + ctxb.w; acc += ab.w * fmaxf(t, 0.2f*t);

        #pragma unroll
        for (int m = 16; m; m >>= 1)
            acc += __shfl_xor_sync(0xffffffffu, acc, m);

        float z0 = __expf((acc + bt0) * s0);
        float z1 = __expf((acc + bt1) * s1);
        zs0 += z0; zs1 += z1;
        if (lane == 0)
            *(float2*)(g_z + (size_t)row * 2) = make_float2(z0, z1);

        f0a.x += xa.x*z0; f0a.y += xa.y*z0; f0a.z += xa.z*z0; f0a.w += xa.w*z0;
        f0b.x += xb.x*z0; f0b.y += xb.y*z0; f0b.z += xb.z*z0; f0b.w += xb.w*z0;
        f1a.x += xa.x*z1; f1a.y += xa.y*z1; f1a.z += xa.z*z1; f1a.w += xa.w*z1;
        f1b.x += xb.x*z1; f1b.y += xb.y*z1; f1b.z += xb.z*z1; f1b.w += xb.w*z1;
    }

    // cross-warp combine via smem atomics (lanes hit distinct addrs in-warp)
    {
        int c0 = 4*lane, c1 = 128 + 4*lane;
        atomicAdd(&sfeat[(c0+0)*2+0], f0a.x); atomicAdd(&sfeat[(c0+0)*2+1], f1a.x);
        atomicAdd(&sfeat[(c0+1)*2+0], f0a.y); atomicAdd(&sfeat[(c0+1)*2+1], f1a.y);
        atomicAdd(&sfeat[(c0+2)*2+0], f0a.z); atomicAdd(&sfeat[(c0+2)*2+1], f1a.z);
        atomicAdd(&sfeat[(c0+3)*2+0], f0a.w); atomicAdd(&sfeat[(c0+3)*2+1], f1a.w);
        atomicAdd(&sfeat[(c1+0)*2+0], f0b.x); atomicAdd(&sfeat[(c1+0)*2+1], f1b.x);
        atomicAdd(&sfeat[(c1+1)*2+0], f0b.y); atomicAdd(&sfeat[(c1+1)*2+1], f1b.y);
        atomicAdd(&sfeat[(c1+2)*2+0], f0b.z); atomicAdd(&sfeat[(c1+2)*2+1], f1b.z);
        atomicAdd(&sfeat[(c1+3)*2+0], f0b.w); atomicAdd(&sfeat[(c1+3)*2+1], f1b.w);
    }
    if (lane == 0) {
        atomicAdd(&szs[0], zs0);
        atomicAdd(&szs[1], zs1);
    }
    __syncthreads();

    // plain-store per-CTA partials (no global atomics, no pre-zero needed)
    for (int i = tid; i < D_*K_; i += THREADS)
        g_featp[(size_t)cta*(D_*K_) + i] = sfeat[i];
    if (tid < K_)
        g_zsump[cta*K_ + tid] = szs[tid];
}

// ---------------------------------------------------------------------------
// Finalize: reduce per-CTA partials, normalize, write outputs, reset counters.
// Output layout: scene_features [B,D,K] then attn_weights [N,K].
// ---------------------------------------------------------------------------
__global__ void finalK(float* __restrict__ out, int out_size)
{
    int i = blockIdx.x * blockDim.x + threadIdx.x;
    if (i < B_) g_cnt[i] = 0;   // reset barrier counters for next replay

    bool both = (out_size >= BDK + NK);
    if (i < BDK) {
        int b = i >> 9;                       // D*K = 512
        int k = i & 1;
        float f = 0.f, zs = 0.f;
        #pragma unroll
        for (int j = 0; j < CPS; j++) {
            f  += g_featp[(size_t)(b*CPS + j)*(D_*K_) + (i & 511)];
            zs += g_zsump[(b*CPS + j)*K_ + k];
        }
        if (both || out_size == BDK) out[i] = f / zs;
    }
    if (both) {
        int j = i;                            // attn weights indexed by j
        if (j < NK) {
            int b = (j >> 1) >> 11;           // OBJS = 2048
            float zs = 0.f;
            #pragma unroll
            for (int c = 0; c < CPS; c++) zs += g_zsump[(b*CPS + c)*K_ + (j & 1)];
            out[BDK + j] = g_z[j] / zs;
        }
    } else if (out_size == NK) {              // attn-only fallback
        if (i < NK) {
            int b = (i >> 1) >> 11;
            float zs = 0.f;
            #pragma unroll
            for (int c = 0; c < CPS; c++) zs += g_zsump[(b*CPS + c)*K_ + (i & 1)];
            out[i] = g_z[i] / zs;
        }
    }
}

// ---------------------------------------------------------------------------
extern "C" void kernel_launch(void* const* d_in, const int* in_sizes, int n_in,
                              void* d_out, int out_size)
{
    const float* x         = (const float*)d_in[0];  // [N, D]
    const int*   num_objs  = (const int*)  d_in[1];  // [B]
    const float* att       = (const float*)d_in[2];  // [1, D]
    const float* scale     = (const float*)d_in[3];  // [K, 1]
    const float* cb        = (const float*)d_in[4];  // [K, D]
    float*       out       = (float*)d_out;

    fusedK<<<NCTA, THREADS>>>(x, att, scale, cb, num_objs);

    int total = NK;                                   // covers BDK too (NK > BDK)
    finalK<<<(total + 255)/256, 256>>>(out, out_size);
}